// round 4
// baseline (speedup 1.0000x reference)
#include <cuda_runtime.h>
#include <cuda_fp16.h>
#include <cstdint>

// ---------------------------------------------------------------------------
// Bahdanau additive attention, B=32, T=2048, H=C=1024.
//   dp[b,c]   = dec[b,:]·W[:,c] + bias[c]                  (fp32)
//   ep[bt,c]  = enc[bt,:]·V[:,c]                           (fp16 mma.sync, fp32 acc)
//   score[bt] = sum_c tanh(dp+ep)·w[c]                     (fused epilogue)
//   align     = softmax_t(score); out[b,h] = sum_t align·enc   (fp32)
// NOTE: harness targets plain sm_103 (no 'a') -> tcgen05/TMA-tile unavailable.
// ---------------------------------------------------------------------------

#define B_DIM 32
#define T_DIM 2048
#define H_DIM 1024
#define C_DIM 1024
#define M_TOTAL (B_DIM * T_DIM)      // 65536

// GEMM tiling
#define CTA_M 128
#define N_CHUNK 128
#define NUM_NC (C_DIM / N_CHUNK)     // 8
#define K_STAGE 64                   // halves per stage (128B rows)
#define NUM_KT (H_DIM / K_STAGE)     // 16
#define GEMM_CTAS (M_TOTAL / CTA_M)  // 512
#define GEMM_THREADS 256             // 8 warps: 4(M) x 2(N), warp tile 32x64

// dynamic smem layout
#define STAGE_BYTES 32768            // A 16KB (128x128B) + B 16KB
#define OFF_B_IN_STAGE 16384
#define OFF_DP (2 * STAGE_BYTES)             // 128 f
#define OFF_W (OFF_DP + 512)                 // 128 f
#define OFF_RED (OFF_W + 512)                // 128 f
#define SMEM_TOTAL (OFF_RED + 512)           // 67072 B

// scratch (static device allocs only; no cudaMalloc allowed)
__device__ __half g_encH[(size_t)M_TOTAL * H_DIM];  // enc in fp16 (128 MB)
__device__ __half g_VtH[(size_t)C_DIM * H_DIM];     // V^T in fp16, K-major
__device__ float g_dp[B_DIM * C_DIM];
__device__ float g_scores[M_TOTAL];
__device__ float g_align[M_TOTAL];

#define SW128(o) ((o) ^ (((o) >> 3) & 0x70))

// ------------------------------- PTX helpers -------------------------------

__device__ __forceinline__ uint32_t smem_u32(const void* p) {
    uint32_t a;
    asm("{ .reg .u64 t; cvta.to.shared.u64 t, %1; cvt.u32.u64 %0, t; }" : "=r"(a) : "l"(p));
    return a;
}

__device__ __forceinline__ void cp16(uint32_t dst, const void* src) {
    asm volatile("cp.async.cg.shared.global [%0], [%1], 16;" :: "r"(dst), "l"(src));
}

__device__ __forceinline__ void ldsm4(uint32_t& r0, uint32_t& r1, uint32_t& r2,
                                      uint32_t& r3, uint32_t addr) {
    asm volatile("ldmatrix.sync.aligned.m8n8.x4.shared.b16 {%0,%1,%2,%3}, [%4];"
                 : "=r"(r0), "=r"(r1), "=r"(r2), "=r"(r3) : "r"(addr));
}

__device__ __forceinline__ void mma16816(float* c, uint32_t a0, uint32_t a1,
                                         uint32_t a2, uint32_t a3,
                                         uint32_t b0, uint32_t b1) {
    asm volatile(
        "mma.sync.aligned.m16n8k16.row.col.f32.f16.f16.f32 "
        "{%0,%1,%2,%3}, {%4,%5,%6,%7}, {%8,%9}, {%0,%1,%2,%3};"
        : "+f"(c[0]), "+f"(c[1]), "+f"(c[2]), "+f"(c[3])
        : "r"(a0), "r"(a1), "r"(a2), "r"(a3), "r"(b0), "r"(b1));
}

__device__ __forceinline__ float tanh_ap(float x) {
    float y;
    asm("tanh.approx.f32 %0, %1;" : "=f"(y) : "f"(x));
    return y;
}

// ------------------------------ prep kernels -------------------------------

__global__ void convert_enc_kernel(const float4* __restrict__ enc4) {
    size_t i = (size_t)blockIdx.x * 256 + threadIdx.x;  // 16M float4s
    float4 v = enc4[i];
    __half2* dst = reinterpret_cast<__half2*>(g_encH);
    dst[2 * i + 0] = __floats2half2_rn(v.x, v.y);
    dst[2 * i + 1] = __floats2half2_rn(v.z, v.w);
}

__global__ void transpose_kernel(const float* __restrict__ V) {
    __shared__ float t[32][33];
    int bx = blockIdx.x, by = blockIdx.y;
    int tx = threadIdx.x, ty = threadIdx.y;
#pragma unroll
    for (int j = 0; j < 32; j += 8)
        t[ty + j][tx] = V[(size_t)(by * 32 + ty + j) * C_DIM + bx * 32 + tx];
    __syncthreads();
#pragma unroll
    for (int j = 0; j < 32; j += 8)
        g_VtH[(size_t)(bx * 32 + ty + j) * H_DIM + by * 32 + tx] =
            __float2half(t[tx][ty + j]);
}

__global__ void dp_kernel(const float* __restrict__ dec, const float* __restrict__ W,
                          const float* __restrict__ bias) {
    __shared__ float sdec[H_DIM];
    int b = blockIdx.y;
    int c = blockIdx.x * 128 + threadIdx.x;
    for (int i = threadIdx.x; i < H_DIM; i += 128) sdec[i] = dec[b * H_DIM + i];
    __syncthreads();
    float acc = bias[c];
#pragma unroll 8
    for (int h = 0; h < H_DIM; h++) acc += sdec[h] * W[(size_t)h * C_DIM + c];
    g_dp[b * C_DIM + c] = acc;
}

__global__ void softmax_kernel() {
    int b = blockIdx.x, tid = threadIdx.x;
    __shared__ float red[256];
    float v[8];
    float m = -1e30f;
#pragma unroll
    for (int k = 0; k < 8; k++) {
        v[k] = g_scores[b * T_DIM + k * 256 + tid];
        m = fmaxf(m, v[k]);
    }
    red[tid] = m;
    __syncthreads();
    for (int s = 128; s > 0; s >>= 1) {
        if (tid < s) red[tid] = fmaxf(red[tid], red[tid + s]);
        __syncthreads();
    }
    m = red[0];
    __syncthreads();
    float sum = 0.f;
#pragma unroll
    for (int k = 0; k < 8; k++) {
        v[k] = __expf(v[k] - m);
        sum += v[k];
    }
    red[tid] = sum;
    __syncthreads();
    for (int s = 128; s > 0; s >>= 1) {
        if (tid < s) red[tid] += red[tid + s];
        __syncthreads();
    }
    float inv = 1.f / red[0];
#pragma unroll
    for (int k = 0; k < 8; k++) g_align[b * T_DIM + k * 256 + tid] = v[k] * inv;
}

__global__ void context_kernel(const float* __restrict__ enc, float* __restrict__ out) {
    int b = blockIdx.y;
    int h = blockIdx.x * 256 + threadIdx.x;
    __shared__ float sa[256];
    float acc = 0.f;
    for (int t0 = 0; t0 < T_DIM; t0 += 256) {
        __syncthreads();
        sa[threadIdx.x] = g_align[b * T_DIM + t0 + threadIdx.x];
        __syncthreads();
#pragma unroll 8
        for (int tt = 0; tt < 256; tt++)
            acc += sa[tt] * enc[((size_t)b * T_DIM + t0 + tt) * H_DIM + h];
    }
    out[b * H_DIM + h] = acc;
}

// ------------------------------- GEMM kernel -------------------------------
// CTA: 128 M-rows, loops N in 8 chunks of 128, K in 16 double-buffered stages
// of 64 halves. 8 warps (4Mx2N), warp tile 32x64, fp16 mma.sync w/ fp32 acc.
// Epilogue fuses tanh(ep+dp)*w into per-row score partials kept in registers.
//
// Swizzle note: inside one 128B smem row, pre-swizzle k-offsets occupy
// disjoint bits (16B sel = bit4, 32B k-step = bits 5-6), and the SW128
// pattern is a pure XOR of bits 4-6. Hence
//   SW128(base + ks*32) == SW128(base) ^ (ks*32)
// so per-kstep ldmatrix addresses are base_swizzled XOR ks*32. (Round-3 bug:
// base_swizzled + ks*32 is WRONG for rows with swizzle bits 5-6 set.)

__global__ void __launch_bounds__(GEMM_THREADS)
gemm_scores_kernel(const float* __restrict__ w_vec) {
    extern __shared__ char smem[];
    uint32_t sb = smem_u32(smem);
    const int tid = threadIdx.x;
    const int lane = tid & 31;
    const int wid = tid >> 5;
    const int warp_m = wid & 3;   // 4 M partitions of 32 rows
    const int warp_n = wid >> 2;  // 2 N partitions of 64 cols

    const int m_base = blockIdx.x * CTA_M;
    const int bidx = m_base >> 11;  // batch index
    float* sdp = (float*)(smem + OFF_DP);
    float* sw = (float*)(smem + OFF_W);
    float* sred = (float*)(smem + OFF_RED);

    // per-lane ldmatrix base addresses (swizzled; XOR ks*32 per k-step)
    const int a_row = warp_m * 32 + (lane & 15);
    const uint32_t a_off0 = SW128(a_row * 128 + (lane >> 4) * 16);          // mi=0
    const uint32_t a_off1 = SW128((a_row + 16) * 128 + (lane >> 4) * 16);   // mi=1
    const int b_row_in = (lane & 7) + ((lane >> 4) & 1) * 8;
    const uint32_t b_koff = ((lane >> 3) & 1) * 16;
    uint32_t b_off[4];
#pragma unroll
    for (int bg = 0; bg < 4; bg++) {
        int brow = warp_n * 64 + bg * 16 + b_row_in;
        b_off[bg] = SW128(brow * 128 + b_koff);
    }

    float acc[2][8][4];
#pragma unroll
    for (int mi = 0; mi < 2; mi++)
#pragma unroll
        for (int ni = 0; ni < 8; ni++)
#pragma unroll
            for (int r = 0; r < 4; r++) acc[mi][ni][r] = 0.f;

    float p[4] = {0.f, 0.f, 0.f, 0.f};  // score partials: (mi,half)

    const __half* encB = g_encH + (size_t)m_base * H_DIM;

    for (int nc = 0; nc < NUM_NC; nc++) {
        if (tid < 128) {
            sdp[tid] = g_dp[bidx * C_DIM + nc * N_CHUNK + tid];
            sw[tid] = w_vec[nc * N_CHUNK + tid];
        }
        const __half* vtB = g_VtH + (size_t)(nc * N_CHUNK) * H_DIM;

        // ---- prologue: stage 0 ----
        {
            uint32_t stage = sb;
#pragma unroll
            for (int i = tid; i < 2048; i += GEMM_THREADS) {
                int row = (i >> 3) & 127, c16 = i & 7;
                if (i < 1024)
                    cp16(stage + SW128(row * 128 + c16 * 16),
                         encB + (size_t)row * H_DIM + c16 * 8);
                else
                    cp16(stage + OFF_B_IN_STAGE + SW128(row * 128 + c16 * 16),
                         vtB + (size_t)row * H_DIM + c16 * 8);
            }
            asm volatile("cp.async.commit_group;" ::: "memory");
        }

#pragma unroll 1
        for (int kt = 0; kt < NUM_KT; kt++) {
            if (kt + 1 < NUM_KT) {
                uint32_t stage = sb + ((kt + 1) & 1) * STAGE_BYTES;
                const __half* ea = encB + (kt + 1) * K_STAGE;
                const __half* vb = vtB + (kt + 1) * K_STAGE;
#pragma unroll
                for (int i = tid; i < 2048; i += GEMM_THREADS) {
                    int row = (i >> 3) & 127, c16 = i & 7;
                    if (i < 1024)
                        cp16(stage + SW128(row * 128 + c16 * 16),
                             ea + (size_t)row * H_DIM + c16 * 8);
                    else
                        cp16(stage + OFF_B_IN_STAGE + SW128(row * 128 + c16 * 16),
                             vb + (size_t)row * H_DIM + c16 * 8);
                }
                asm volatile("cp.async.commit_group;" ::: "memory");
                asm volatile("cp.async.wait_group 1;" ::: "memory");
            } else {
                asm volatile("cp.async.wait_group 0;" ::: "memory");
            }
            __syncthreads();

            uint32_t stA = sb + (kt & 1) * STAGE_BYTES;
            uint32_t stB = stA + OFF_B_IN_STAGE;
#pragma unroll
            for (int ks = 0; ks < 4; ks++) {  // 4 x k16 per stage
                const uint32_t kx = (uint32_t)(ks * 32);
                uint32_t af[2][4];
                ldsm4(af[0][0], af[0][1], af[0][2], af[0][3], stA + (a_off0 ^ kx));
                ldsm4(af[1][0], af[1][1], af[1][2], af[1][3], stA + (a_off1 ^ kx));
                uint32_t bf[4][4];
#pragma unroll
                for (int bg = 0; bg < 4; bg++)
                    ldsm4(bf[bg][0], bf[bg][1], bf[bg][2], bf[bg][3],
                          stB + (b_off[bg] ^ kx));
#pragma unroll
                for (int mi = 0; mi < 2; mi++)
#pragma unroll
                    for (int ni = 0; ni < 8; ni++) {
                        int bg = ni >> 1, sub = (ni & 1) * 2;
                        mma16816(acc[mi][ni], af[mi][0], af[mi][1], af[mi][2],
                                 af[mi][3], bf[bg][sub], bf[bg][sub + 1]);
                    }
            }
            __syncthreads();
        }

        // ---- fused epilogue: score += tanh(ep+dp)·w, reset accums ----
#pragma unroll
        for (int mi = 0; mi < 2; mi++)
#pragma unroll
            for (int ni = 0; ni < 8; ni++) {
                int col = warp_n * 64 + ni * 8 + (lane & 3) * 2;
                float d0 = sdp[col], d1 = sdp[col + 1];
                float w0 = sw[col], w1 = sw[col + 1];
                float* c = acc[mi][ni];
                p[mi * 2 + 0] += tanh_ap(c[0] + d0) * w0 + tanh_ap(c[1] + d1) * w1;
                p[mi * 2 + 1] += tanh_ap(c[2] + d0) * w0 + tanh_ap(c[3] + d1) * w1;
                c[0] = 0.f; c[1] = 0.f; c[2] = 0.f; c[3] = 0.f;
            }
        __syncthreads();  // sdp/sw reload next nc
    }

    // ---- final reduction: over lane quads, then over warp_n pairs ----
#pragma unroll
    for (int j = 0; j < 4; j++) {
        p[j] += __shfl_xor_sync(0xFFFFFFFF, p[j], 1);
        p[j] += __shfl_xor_sync(0xFFFFFFFF, p[j], 2);
    }
    if (warp_n == 0 && (lane & 3) == 0) {
#pragma unroll
        for (int j = 0; j < 4; j++) {
            int row = warp_m * 32 + (j >> 1) * 16 + (j & 1) * 8 + (lane >> 2);
            sred[row] = p[j];
        }
    }
    __syncthreads();
    if (warp_n == 1 && (lane & 3) == 0) {
#pragma unroll
        for (int j = 0; j < 4; j++) {
            int row = warp_m * 32 + (j >> 1) * 16 + (j & 1) * 8 + (lane >> 2);
            sred[row] += p[j];
        }
    }
    __syncthreads();
    if (tid < 128) g_scores[m_base + tid] = sred[tid];
}

// -------------------------------- launcher ---------------------------------

extern "C" void kernel_launch(void* const* d_in, const int* in_sizes, int n_in,
                              void* d_out, int out_size) {
    const float* dec  = (const float*)d_in[0];  // [32,1,1024]
    const float* enc  = (const float*)d_in[1];  // [32,2048,1024]
    const float* W    = (const float*)d_in[2];  // [1024,1024]
    const float* V    = (const float*)d_in[3];  // [1024,1024]
    const float* bias = (const float*)d_in[4];  // [1024]
    const float* w    = (const float*)d_in[5];  // [1024,1]
    float* out = (float*)d_out;                 // [32,1024]

    cudaFuncSetAttribute(gemm_scores_kernel,
                         cudaFuncAttributeMaxDynamicSharedMemorySize, SMEM_TOTAL);

    convert_enc_kernel<<<65536, 256>>>((const float4*)enc);
    transpose_kernel<<<dim3(32, 32), dim3(32, 8)>>>(V);
    dp_kernel<<<dim3(8, 32), 128>>>(dec, W, bias);
    gemm_scores_kernel<<<GEMM_CTAS, GEMM_THREADS, SMEM_TOTAL>>>(w);
    softmax_kernel<<<32, 256>>>();
    context_kernel<<<dim3(4, 32), 256>>>(enc, out);
}

// round 5
// speedup vs baseline: 1.0465x; 1.0465x over previous
#include <cuda_runtime.h>
#include <cuda_fp16.h>
#include <cstdint>

// ---------------------------------------------------------------------------
// Bahdanau additive attention, B=32, T=2048, H=C=1024.
// GEMM producer rewritten: gmem holds PRE-TILED, PRE-SWIZZLED fp16 stages so
// each 16KB k-stage is one contiguous cp.async.bulk (sm_90 baseline feature)
// into an mbarrier — removes the 262K-instruction LDGSTS issue bottleneck
// that capped tensor pipe at 62.7% in round 4.
// ---------------------------------------------------------------------------

#define B_DIM 32
#define T_DIM 2048
#define H_DIM 1024
#define C_DIM 1024
#define M_TOTAL (B_DIM * T_DIM)      // 65536

#define CTA_M 128
#define N_CHUNK 128
#define NUM_NC (C_DIM / N_CHUNK)     // 8
#define K_STAGE 64                   // halves per stage row chunk
#define NUM_KT (H_DIM / K_STAGE)     // 16
#define NUM_S (NUM_NC * NUM_KT)      // 128 logical stages
#define GEMM_CTAS (M_TOTAL / CTA_M)  // 512
#define GEMM_THREADS 256             // 8 warps: 4(M) x 2(N)

#define STAGE_BYTES 32768            // A 16KB + B 16KB
#define NSTAGES 3
#define OFF_MBAR (NSTAGES * STAGE_BYTES)       // 98304, 3 x 8B
#define OFF_DP (OFF_MBAR + 64)                 // 128 f
#define OFF_W (OFF_DP + 512)
#define OFF_RED (OFF_W + 512)
#define SMEM_TOTAL (OFF_RED + 512)             // 99904

// scratch (static device arrays; no cudaMalloc allowed)
// Tiled+swizzled stage images, 16KB each:
//  encHT: [mtile 0..511][kt 0..15] -> 128 rows x 64 halves, SW128-swizzled
//  vtHT : [nc 0..7][kt 0..15]     -> 128 n-rows x 64 halves, SW128-swizzled
__device__ __align__(1024) __half g_encHT[(size_t)M_TOTAL * H_DIM];
__device__ __align__(1024) __half g_VtHT[(size_t)C_DIM * H_DIM];
__device__ float g_dp[B_DIM * C_DIM];
__device__ float g_scores[M_TOTAL];
__device__ float g_align[M_TOTAL];

#define SW128(o) ((o) ^ (((o) >> 3) & 0x70))

// ------------------------------- PTX helpers -------------------------------

__device__ __forceinline__ uint32_t smem_u32(const void* p) {
    uint32_t a;
    asm("{ .reg .u64 t; cvta.to.shared.u64 t, %1; cvt.u32.u64 %0, t; }" : "=r"(a) : "l"(p));
    return a;
}

__device__ __forceinline__ void bulk_cp(uint32_t dst, const void* src,
                                        uint32_t bytes, uint32_t mbar) {
    asm volatile(
        "cp.async.bulk.shared::cluster.global.mbarrier::complete_tx::bytes "
        "[%0], [%1], %2, [%3];"
        :: "r"(dst), "l"(src), "r"(bytes), "r"(mbar) : "memory");
}

__device__ __forceinline__ void mbar_init(uint32_t a, uint32_t cnt) {
    asm volatile("mbarrier.init.shared.b64 [%0], %1;" :: "r"(a), "r"(cnt) : "memory");
}

__device__ __forceinline__ void mbar_expect_tx(uint32_t a, uint32_t n) {
    asm volatile("mbarrier.arrive.expect_tx.shared.b64 _, [%0], %1;"
                 :: "r"(a), "r"(n) : "memory");
}

__device__ __forceinline__ void mbar_wait(uint32_t a, uint32_t phase) {
    asm volatile(
        "{\n\t.reg .pred P;\n"
        "WL_%=:\n\t"
        "mbarrier.try_wait.parity.acquire.cta.shared::cta.b64 P, [%0], %1, 0x989680;\n\t"
        "@P bra WD_%=;\n\t"
        "bra WL_%=;\n"
        "WD_%=:\n\t}"
        :: "r"(a), "r"(phase) : "memory");
}

__device__ __forceinline__ void ldsm4(uint32_t& r0, uint32_t& r1, uint32_t& r2,
                                      uint32_t& r3, uint32_t addr) {
    asm volatile("ldmatrix.sync.aligned.m8n8.x4.shared.b16 {%0,%1,%2,%3}, [%4];"
                 : "=r"(r0), "=r"(r1), "=r"(r2), "=r"(r3) : "r"(addr));
}

__device__ __forceinline__ void mma16816(float* c, uint32_t a0, uint32_t a1,
                                         uint32_t a2, uint32_t a3,
                                         uint32_t b0, uint32_t b1) {
    asm volatile(
        "mma.sync.aligned.m16n8k16.row.col.f32.f16.f16.f32 "
        "{%0,%1,%2,%3}, {%4,%5,%6,%7}, {%8,%9}, {%0,%1,%2,%3};"
        : "+f"(c[0]), "+f"(c[1]), "+f"(c[2]), "+f"(c[3])
        : "r"(a0), "r"(a1), "r"(a2), "r"(a3), "r"(b0), "r"(b1));
}

__device__ __forceinline__ float tanh_ap(float x) {
    float y;
    asm("tanh.approx.f32 %0, %1;" : "=f"(y) : "f"(x));
    return y;
}

// ------------------------------ prep kernels -------------------------------

// One thread per 16B output chunk (8 halves). 8M chunks, grid 32768 x 256.
__global__ void convert_enc_kernel(const float* __restrict__ enc) {
    size_t i = (size_t)blockIdx.x * 256 + threadIdx.x;
    int c16 = (int)(i & 7);
    int row = (int)((i >> 3) & 127);
    int kt = (int)((i >> 10) & 15);
    int mtile = (int)(i >> 14);
    int m = mtile * 128 + row;
    int k = kt * 64 + c16 * 8;
    const float4* s = (const float4*)(enc + (size_t)m * H_DIM + k);
    float4 v0 = s[0], v1 = s[1];
    __half2 h0 = __floats2half2_rn(v0.x, v0.y);
    __half2 h1 = __floats2half2_rn(v0.z, v0.w);
    __half2 h2 = __floats2half2_rn(v1.x, v1.y);
    __half2 h3 = __floats2half2_rn(v1.z, v1.w);
    uint4 u;
    u.x = *(uint32_t*)&h0; u.y = *(uint32_t*)&h1;
    u.z = *(uint32_t*)&h2; u.w = *(uint32_t*)&h3;
    char* dst = (char*)g_encHT + (((size_t)mtile * 16 + kt) << 14) +
                SW128(row * 128 + c16 * 16);
    *(uint4*)dst = u;
}

// V[h,c] -> tiled swizzled Vt stages (n-major rows, k contiguous per row).
__global__ void transpose_kernel(const float* __restrict__ V) {
    __shared__ float t[32][33];
    int bx = blockIdx.x, by = blockIdx.y;
    int tx = threadIdx.x, ty = threadIdx.y;
#pragma unroll
    for (int j = 0; j < 32; j += 8)
        t[ty + j][tx] = V[(size_t)(by * 32 + ty + j) * C_DIM + bx * 32 + tx];
    __syncthreads();
#pragma unroll
    for (int j = 0; j < 32; j += 8) {
        int n = bx * 32 + ty + j;   // output row (c of V)
        int k = by * 32 + tx;       // output col (h of V)
        int nc = n >> 7, row = n & 127;
        int kt = k >> 6, c16 = (k >> 3) & 7, r8 = k & 7;
        size_t off = (((size_t)nc * 16 + kt) << 14) +
                     SW128(row * 128 + c16 * 16) + r8 * 2;
        *(__half*)((char*)g_VtHT + off) = __float2half(t[tx][ty + j]);
    }
}

__global__ void dp_kernel(const float* __restrict__ dec, const float* __restrict__ W,
                          const float* __restrict__ bias) {
    __shared__ float sdec[H_DIM];
    int b = blockIdx.y;
    int c = blockIdx.x * 128 + threadIdx.x;
    for (int i = threadIdx.x; i < H_DIM; i += 128) sdec[i] = dec[b * H_DIM + i];
    __syncthreads();
    float acc = bias[c];
#pragma unroll 8
    for (int h = 0; h < H_DIM; h++) acc += sdec[h] * W[(size_t)h * C_DIM + c];
    g_dp[b * C_DIM + c] = acc;
}

__global__ void softmax_kernel() {
    int b = blockIdx.x, tid = threadIdx.x;
    __shared__ float red[256];
    float v[8];
    float m = -1e30f;
#pragma unroll
    for (int k = 0; k < 8; k++) {
        v[k] = g_scores[b * T_DIM + k * 256 + tid];
        m = fmaxf(m, v[k]);
    }
    red[tid] = m;
    __syncthreads();
    for (int s = 128; s > 0; s >>= 1) {
        if (tid < s) red[tid] = fmaxf(red[tid], red[tid + s]);
        __syncthreads();
    }
    m = red[0];
    __syncthreads();
    float sum = 0.f;
#pragma unroll
    for (int k = 0; k < 8; k++) {
        v[k] = __expf(v[k] - m);
        sum += v[k];
    }
    red[tid] = sum;
    __syncthreads();
    for (int s = 128; s > 0; s >>= 1) {
        if (tid < s) red[tid] += red[tid + s];
        __syncthreads();
    }
    float inv = 1.f / red[0];
#pragma unroll
    for (int k = 0; k < 8; k++) g_align[b * T_DIM + k * 256 + tid] = v[k] * inv;
}

__global__ void context_kernel(const float* __restrict__ enc, float* __restrict__ out) {
    int b = blockIdx.y;
    int h = blockIdx.x * 256 + threadIdx.x;
    __shared__ float sa[256];
    float acc = 0.f;
    for (int t0 = 0; t0 < T_DIM; t0 += 256) {
        __syncthreads();
        sa[threadIdx.x] = g_align[b * T_DIM + t0 + threadIdx.x];
        __syncthreads();
#pragma unroll 8
        for (int tt = 0; tt < 256; tt++)
            acc += sa[tt] * enc[((size_t)b * T_DIM + t0 + tt) * H_DIM + h];
    }
    out[b * H_DIM + h] = acc;
}

// ------------------------------- GEMM kernel -------------------------------
// 128 logical stages (nc 0..7 x kt 0..15). 3-stage smem ring; one elected
// thread bulk-copies A(16KB)+B(16KB) per stage with expect_tx(32KB).
// One __syncthreads per stage. 8 warps (4Mx2N), warp tile 32x64,
// fp16 mma.sync fp32 acc, fused tanh(ep+dp)*w epilogue at kt==15.

__global__ void __launch_bounds__(GEMM_THREADS, 2)
gemm_scores_kernel(const float* __restrict__ w_vec) {
    extern __shared__ __align__(1024) char smem[];
    uint32_t sb = smem_u32(smem);
    const int tid = threadIdx.x;
    const int lane = tid & 31;
    const int wid = tid >> 5;
    const int warp_m = wid & 3;
    const int warp_n = wid >> 2;

    const int m_base = blockIdx.x * CTA_M;
    const int bidx = m_base >> 11;
    float* sdp = (float*)(smem + OFF_DP);
    float* sw = (float*)(smem + OFF_W);
    float* sred = (float*)(smem + OFF_RED);

    // ldmatrix base addresses (swizzled; XOR ks*32 per k16-step)
    const int a_row = warp_m * 32 + (lane & 15);
    const uint32_t a_off0 = SW128(a_row * 128 + (lane >> 4) * 16);
    const uint32_t a_off1 = SW128((a_row + 16) * 128 + (lane >> 4) * 16);
    const int b_row_in = (lane & 7) + ((lane >> 4) & 1) * 8;
    const uint32_t b_koff = ((lane >> 3) & 1) * 16;
    uint32_t b_off[4];
#pragma unroll
    for (int bg = 0; bg < 4; bg++) {
        int brow = warp_n * 64 + bg * 16 + b_row_in;
        b_off[bg] = SW128(brow * 128 + b_koff);
    }

    const char* encT = (const char*)g_encHT + ((size_t)blockIdx.x << 18);  // *16*16384
    const char* vtT = (const char*)g_VtHT;

    if (tid == 0) {
#pragma unroll
        for (int b = 0; b < NSTAGES; b++) mbar_init(sb + OFF_MBAR + b * 8, 1);
    }
    __syncthreads();

    // prologue: issue stages 0,1
    if (tid == 0) {
#pragma unroll
        for (int s = 0; s < NSTAGES - 1; s++) {
            uint32_t mb = sb + OFF_MBAR + (s % NSTAGES) * 8;
            uint32_t dst = sb + (s % NSTAGES) * STAGE_BYTES;
            mbar_expect_tx(mb, STAGE_BYTES);
            bulk_cp(dst, encT + (size_t)(s & 15) * 16384, 16384, mb);
            bulk_cp(dst + 16384, vtT + ((size_t)s << 14), 16384, mb);
        }
    }

    float acc[2][8][4];
#pragma unroll
    for (int mi = 0; mi < 2; mi++)
#pragma unroll
        for (int ni = 0; ni < 8; ni++)
#pragma unroll
            for (int r = 0; r < 4; r++) acc[mi][ni][r] = 0.f;
    float p[4] = {0.f, 0.f, 0.f, 0.f};

#pragma unroll 1
    for (int s = 0; s < NUM_S; s++) {
        const int kt = s & 15;
        const int nc = s >> 4;
        // issue stage s+2 (its buffer held stage s-1, released by the
        // __syncthreads at the end of iteration s-1)
        if (tid == 0 && s + NSTAGES - 1 < NUM_S) {
            int sp = s + NSTAGES - 1;
            uint32_t mb = sb + OFF_MBAR + (sp % NSTAGES) * 8;
            uint32_t dst = sb + (sp % NSTAGES) * STAGE_BYTES;
            mbar_expect_tx(mb, STAGE_BYTES);
            bulk_cp(dst, encT + (size_t)(sp & 15) * 16384, 16384, mb);
            bulk_cp(dst + 16384, vtT + ((size_t)sp << 14), 16384, mb);
        }
        if (kt == 0 && tid < 128) {
            sdp[tid] = g_dp[bidx * C_DIM + nc * N_CHUNK + tid];
            sw[tid] = w_vec[nc * N_CHUNK + tid];
        }
        mbar_wait(sb + OFF_MBAR + (s % NSTAGES) * 8, (s / NSTAGES) & 1);

        uint32_t stA = sb + (s % NSTAGES) * STAGE_BYTES;
        uint32_t stB = stA + 16384;
#pragma unroll
        for (int ks = 0; ks < 4; ks++) {
            const uint32_t kx = (uint32_t)(ks * 32);
            uint32_t af[2][4];
            ldsm4(af[0][0], af[0][1], af[0][2], af[0][3], stA + (a_off0 ^ kx));
            ldsm4(af[1][0], af[1][1], af[1][2], af[1][3], stA + (a_off1 ^ kx));
            uint32_t bf[4][4];
#pragma unroll
            for (int bg = 0; bg < 4; bg++)
                ldsm4(bf[bg][0], bf[bg][1], bf[bg][2], bf[bg][3],
                      stB + (b_off[bg] ^ kx));
#pragma unroll
            for (int mi = 0; mi < 2; mi++)
#pragma unroll
                for (int ni = 0; ni < 8; ni++) {
                    int bg = ni >> 1, sub = (ni & 1) * 2;
                    mma16816(acc[mi][ni], af[mi][0], af[mi][1], af[mi][2],
                             af[mi][3], bf[bg][sub], bf[bg][sub + 1]);
                }
        }

        if (kt == 15) {
            // fused epilogue: score += tanh(ep+dp)*w; reset accumulators
#pragma unroll
            for (int mi = 0; mi < 2; mi++)
#pragma unroll
                for (int ni = 0; ni < 8; ni++) {
                    int col = warp_n * 64 + ni * 8 + (lane & 3) * 2;
                    float d0 = sdp[col], d1 = sdp[col + 1];
                    float w0 = sw[col], w1 = sw[col + 1];
                    float* c = acc[mi][ni];
                    p[mi * 2 + 0] += tanh_ap(c[0] + d0) * w0 + tanh_ap(c[1] + d1) * w1;
                    p[mi * 2 + 1] += tanh_ap(c[2] + d0) * w0 + tanh_ap(c[3] + d1) * w1;
                    c[0] = 0.f; c[1] = 0.f; c[2] = 0.f; c[3] = 0.f;
                }
        }
        __syncthreads();  // release buffer s%NSTAGES for reuse
    }

    // final reduction: lane quads, then warp_n pairs
#pragma unroll
    for (int j = 0; j < 4; j++) {
        p[j] += __shfl_xor_sync(0xFFFFFFFF, p[j], 1);
        p[j] += __shfl_xor_sync(0xFFFFFFFF, p[j], 2);
    }
    if (warp_n == 0 && (lane & 3) == 0) {
#pragma unroll
        for (int j = 0; j < 4; j++) {
            int row = warp_m * 32 + (j >> 1) * 16 + (j & 1) * 8 + (lane >> 2);
            sred[row] = p[j];
        }
    }
    __syncthreads();
    if (warp_n == 1 && (lane & 3) == 0) {
#pragma unroll
        for (int j = 0; j < 4; j++) {
            int row = warp_m * 32 + (j >> 1) * 16 + (j & 1) * 8 + (lane >> 2);
            sred[row] += p[j];
        }
    }
    __syncthreads();
    if (tid < 128) g_scores[m_base + tid] = sred[tid];
}

// -------------------------------- launcher ---------------------------------

extern "C" void kernel_launch(void* const* d_in, const int* in_sizes, int n_in,
                              void* d_out, int out_size) {
    const float* dec  = (const float*)d_in[0];  // [32,1,1024]
    const float* enc  = (const float*)d_in[1];  // [32,2048,1024]
    const float* W    = (const float*)d_in[2];  // [1024,1024]
    const float* V    = (const float*)d_in[3];  // [1024,1024]
    const float* bias = (const float*)d_in[4];  // [1024]
    const float* w    = (const float*)d_in[5];  // [1024,1]
    float* out = (float*)d_out;                 // [32,1024]

    cudaFuncSetAttribute(gemm_scores_kernel,
                         cudaFuncAttributeMaxDynamicSharedMemorySize, SMEM_TOTAL);

    convert_enc_kernel<<<32768, 256>>>(enc);
    transpose_kernel<<<dim3(32, 32), dim3(32, 8)>>>(V);
    dp_kernel<<<dim3(8, 32), 128>>>(dec, W, bias);
    gemm_scores_kernel<<<GEMM_CTAS, GEMM_THREADS, SMEM_TOTAL>>>(w);
    softmax_kernel<<<32, 256>>>();
    context_kernel<<<dim3(4, 32), 256>>>(enc, out);
}

// round 6
// speedup vs baseline: 1.0675x; 1.0201x over previous
#include <cuda_runtime.h>
#include <cuda_fp16.h>
#include <cstdint>

// ---------------------------------------------------------------------------
// Bahdanau additive attention, B=32, T=2048, H=C=1024.
// R6: GEMM warp grid 2Mx2N (warp tile 64x64, 128 thr/CTA) to cut smem LDSM
// amplification 96KB->64KB per stage (crossbar-bound per R5 ncu: L1=53.7%).
// dp_kernel split two-phase so W is read once (was x32).
// ---------------------------------------------------------------------------

#define B_DIM 32
#define T_DIM 2048
#define H_DIM 1024
#define C_DIM 1024
#define M_TOTAL (B_DIM * T_DIM)      // 65536

#define CTA_M 128
#define N_CHUNK 128
#define NUM_NC (C_DIM / N_CHUNK)     // 8
#define K_STAGE 64
#define NUM_KT (H_DIM / K_STAGE)     // 16
#define NUM_S (NUM_NC * NUM_KT)      // 128 logical stages
#define GEMM_CTAS (M_TOTAL / CTA_M)  // 512
#define GEMM_THREADS 128             // 4 warps: 2(M) x 2(N), warp tile 64x64

#define STAGE_BYTES 32768            // A 16KB + B 16KB
#define NSTAGES 3
#define OFF_MBAR (NSTAGES * STAGE_BYTES)
#define OFF_DP (OFF_MBAR + 64)
#define OFF_W (OFF_DP + 512)
#define OFF_RED (OFF_W + 512)
#define SMEM_TOTAL (OFF_RED + 512)   // 99904 (2 CTAs/SM: 199808 <= 227KB)

// scratch (static device arrays; no cudaMalloc allowed)
__device__ __align__(1024) __half g_encHT[(size_t)M_TOTAL * H_DIM];
__device__ __align__(1024) __half g_VtHT[(size_t)C_DIM * H_DIM];
__device__ float g_dpp[4][B_DIM * C_DIM];   // per-h-chunk partials
__device__ float g_dp[B_DIM * C_DIM];
__device__ float g_scores[M_TOTAL];
__device__ float g_align[M_TOTAL];

#define SW128(o) ((o) ^ (((o) >> 3) & 0x70))

// ------------------------------- PTX helpers -------------------------------

__device__ __forceinline__ uint32_t smem_u32(const void* p) {
    uint32_t a;
    asm("{ .reg .u64 t; cvta.to.shared.u64 t, %1; cvt.u32.u64 %0, t; }" : "=r"(a) : "l"(p));
    return a;
}

__device__ __forceinline__ void bulk_cp(uint32_t dst, const void* src,
                                        uint32_t bytes, uint32_t mbar) {
    asm volatile(
        "cp.async.bulk.shared::cluster.global.mbarrier::complete_tx::bytes "
        "[%0], [%1], %2, [%3];"
        :: "r"(dst), "l"(src), "r"(bytes), "r"(mbar) : "memory");
}

__device__ __forceinline__ void mbar_init(uint32_t a, uint32_t cnt) {
    asm volatile("mbarrier.init.shared.b64 [%0], %1;" :: "r"(a), "r"(cnt) : "memory");
}

__device__ __forceinline__ void mbar_expect_tx(uint32_t a, uint32_t n) {
    asm volatile("mbarrier.arrive.expect_tx.shared.b64 _, [%0], %1;"
                 :: "r"(a), "r"(n) : "memory");
}

__device__ __forceinline__ void mbar_wait(uint32_t a, uint32_t phase) {
    asm volatile(
        "{\n\t.reg .pred P;\n"
        "WL_%=:\n\t"
        "mbarrier.try_wait.parity.acquire.cta.shared::cta.b64 P, [%0], %1, 0x989680;\n\t"
        "@P bra WD_%=;\n\t"
        "bra WL_%=;\n"
        "WD_%=:\n\t}"
        :: "r"(a), "r"(phase) : "memory");
}

__device__ __forceinline__ void ldsm4(uint32_t& r0, uint32_t& r1, uint32_t& r2,
                                      uint32_t& r3, uint32_t addr) {
    asm volatile("ldmatrix.sync.aligned.m8n8.x4.shared.b16 {%0,%1,%2,%3}, [%4];"
                 : "=r"(r0), "=r"(r1), "=r"(r2), "=r"(r3) : "r"(addr));
}

__device__ __forceinline__ void mma16816(float* c, uint32_t a0, uint32_t a1,
                                         uint32_t a2, uint32_t a3,
                                         uint32_t b0, uint32_t b1) {
    asm volatile(
        "mma.sync.aligned.m16n8k16.row.col.f32.f16.f16.f32 "
        "{%0,%1,%2,%3}, {%4,%5,%6,%7}, {%8,%9}, {%0,%1,%2,%3};"
        : "+f"(c[0]), "+f"(c[1]), "+f"(c[2]), "+f"(c[3])
        : "r"(a0), "r"(a1), "r"(a2), "r"(a3), "r"(b0), "r"(b1));
}

__device__ __forceinline__ float tanh_ap(float x) {
    float y;
    asm("tanh.approx.f32 %0, %1;" : "=f"(y) : "f"(x));
    return y;
}

// ------------------------------ prep kernels -------------------------------

__global__ void convert_enc_kernel(const float* __restrict__ enc) {
    size_t i = (size_t)blockIdx.x * 256 + threadIdx.x;
    int c16 = (int)(i & 7);
    int row = (int)((i >> 3) & 127);
    int kt = (int)((i >> 10) & 15);
    int mtile = (int)(i >> 14);
    int m = mtile * 128 + row;
    int k = kt * 64 + c16 * 8;
    const float4* s = (const float4*)(enc + (size_t)m * H_DIM + k);
    float4 v0 = s[0], v1 = s[1];
    __half2 h0 = __floats2half2_rn(v0.x, v0.y);
    __half2 h1 = __floats2half2_rn(v0.z, v0.w);
    __half2 h2 = __floats2half2_rn(v1.x, v1.y);
    __half2 h3 = __floats2half2_rn(v1.z, v1.w);
    uint4 u;
    u.x = *(uint32_t*)&h0; u.y = *(uint32_t*)&h1;
    u.z = *(uint32_t*)&h2; u.w = *(uint32_t*)&h3;
    char* dst = (char*)g_encHT + (((size_t)mtile * 16 + kt) << 14) +
                SW128(row * 128 + c16 * 16);
    *(uint4*)dst = u;
}

__global__ void transpose_kernel(const float* __restrict__ V) {
    __shared__ float t[32][33];
    int bx = blockIdx.x, by = blockIdx.y;
    int tx = threadIdx.x, ty = threadIdx.y;
#pragma unroll
    for (int j = 0; j < 32; j += 8)
        t[ty + j][tx] = V[(size_t)(by * 32 + ty + j) * C_DIM + bx * 32 + tx];
    __syncthreads();
#pragma unroll
    for (int j = 0; j < 32; j += 8) {
        int n = bx * 32 + ty + j;
        int k = by * 32 + tx;
        int nc = n >> 7, row = n & 127;
        int kt = k >> 6, c16 = (k >> 3) & 7, r8 = k & 7;
        size_t off = (((size_t)nc * 16 + kt) << 14) +
                     SW128(row * 128 + c16 * 16) + r8 * 2;
        *(__half*)((char*)g_VtHT + off) = __float2half(t[tx][ty + j]);
    }
}

// dp phase 1: block (cb, hc) accumulates 256-h slice for its 128 c-columns,
// all 32 batches in registers; W read exactly once across the grid.
__global__ void dp_part_kernel(const float* __restrict__ dec,
                               const float* __restrict__ W) {
    __shared__ float sdec[32 * 256];
    int cb = blockIdx.x, hc = blockIdx.y;
    int tid = threadIdx.x;
    for (int i = tid; i < 32 * 256; i += 128) {
        int b = i >> 8, h = i & 255;
        sdec[i] = dec[b * H_DIM + hc * 256 + h];
    }
    __syncthreads();
    int c = cb * 128 + tid;
    float acc[32];
#pragma unroll
    for (int b = 0; b < 32; b++) acc[b] = 0.f;
#pragma unroll 4
    for (int h = 0; h < 256; h++) {
        float wv = W[(size_t)(hc * 256 + h) * C_DIM + c];
#pragma unroll
        for (int b = 0; b < 32; b++) acc[b] += sdec[b * 256 + h] * wv;
    }
#pragma unroll
    for (int b = 0; b < 32; b++) g_dpp[hc][b * C_DIM + c] = acc[b];
}

__global__ void dp_reduce_kernel(const float* __restrict__ bias) {
    int i = blockIdx.x * 256 + threadIdx.x;  // 32768 entries
    int c = i & (C_DIM - 1);
    g_dp[i] = bias[c] + g_dpp[0][i] + g_dpp[1][i] + g_dpp[2][i] + g_dpp[3][i];
}

__global__ void softmax_kernel() {
    int b = blockIdx.x, tid = threadIdx.x;
    __shared__ float red[256];
    float v[8];
    float m = -1e30f;
#pragma unroll
    for (int k = 0; k < 8; k++) {
        v[k] = g_scores[b * T_DIM + k * 256 + tid];
        m = fmaxf(m, v[k]);
    }
    red[tid] = m;
    __syncthreads();
    for (int s = 128; s > 0; s >>= 1) {
        if (tid < s) red[tid] = fmaxf(red[tid], red[tid + s]);
        __syncthreads();
    }
    m = red[0];
    __syncthreads();
    float sum = 0.f;
#pragma unroll
    for (int k = 0; k < 8; k++) {
        v[k] = __expf(v[k] - m);
        sum += v[k];
    }
    red[tid] = sum;
    __syncthreads();
    for (int s = 128; s > 0; s >>= 1) {
        if (tid < s) red[tid] += red[tid + s];
        __syncthreads();
    }
    float inv = 1.f / red[0];
#pragma unroll
    for (int k = 0; k < 8; k++) g_align[b * T_DIM + k * 256 + tid] = v[k] * inv;
}

__global__ void context_kernel(const float* __restrict__ enc, float* __restrict__ out) {
    int b = blockIdx.y;
    int h = blockIdx.x * 256 + threadIdx.x;
    __shared__ float sa[256];
    float acc = 0.f;
    for (int t0 = 0; t0 < T_DIM; t0 += 256) {
        __syncthreads();
        sa[threadIdx.x] = g_align[b * T_DIM + t0 + threadIdx.x];
        __syncthreads();
#pragma unroll 8
        for (int tt = 0; tt < 256; tt++)
            acc += sa[tt] * enc[((size_t)b * T_DIM + t0 + tt) * H_DIM + h];
    }
    out[b * H_DIM + h] = acc;
}

// ------------------------------- GEMM kernel -------------------------------
// 4 warps (2Mx2N), warp tile 64x64. 3-stage bulk-copy ring (one elected
// thread, expect_tx 32KB). Per k16-step: 4 A + 4 B ldsm4, 32 mma.
// Fused tanh(ep+dp)*w epilogue at kt==15.

__global__ void __launch_bounds__(GEMM_THREADS)
gemm_scores_kernel(const float* __restrict__ w_vec) {
    extern __shared__ __align__(1024) char smem[];
    uint32_t sb = smem_u32(smem);
    const int tid = threadIdx.x;
    const int lane = tid & 31;
    const int wid = tid >> 5;
    const int warp_m = wid & 1;   // 2 M partitions of 64 rows
    const int warp_n = wid >> 1;  // 2 N partitions of 64 cols

    const int m_base = blockIdx.x * CTA_M;
    const int bidx = m_base >> 11;
    float* sdp = (float*)(smem + OFF_DP);
    float* sw = (float*)(smem + OFF_W);
    float* sred = (float*)(smem + OFF_RED);

    // ldmatrix base addresses (swizzled; XOR ks*32 per k16-step)
    uint32_t a_off[4];
#pragma unroll
    for (int mi = 0; mi < 4; mi++) {
        int ar = warp_m * 64 + mi * 16 + (lane & 15);
        a_off[mi] = SW128(ar * 128 + (lane >> 4) * 16);
    }
    const int b_row_in = (lane & 7) + ((lane >> 4) & 1) * 8;
    const uint32_t b_koff = ((lane >> 3) & 1) * 16;
    uint32_t b_off[4];
#pragma unroll
    for (int bg = 0; bg < 4; bg++) {
        int brow = warp_n * 64 + bg * 16 + b_row_in;
        b_off[bg] = SW128(brow * 128 + b_koff);
    }

    const char* encT = (const char*)g_encHT + ((size_t)blockIdx.x << 18);
    const char* vtT = (const char*)g_VtHT;

    if (tid == 0) {
#pragma unroll
        for (int b = 0; b < NSTAGES; b++) mbar_init(sb + OFF_MBAR + b * 8, 1);
    }
    __syncthreads();

    if (tid == 0) {
#pragma unroll
        for (int s = 0; s < NSTAGES - 1; s++) {
            uint32_t mb = sb + OFF_MBAR + s * 8;
            uint32_t dst = sb + s * STAGE_BYTES;
            mbar_expect_tx(mb, STAGE_BYTES);
            bulk_cp(dst, encT + (size_t)(s & 15) * 16384, 16384, mb);
            bulk_cp(dst + 16384, vtT + ((size_t)s << 14), 16384, mb);
        }
    }

    float acc[4][8][4];
#pragma unroll
    for (int mi = 0; mi < 4; mi++)
#pragma unroll
        for (int ni = 0; ni < 8; ni++)
#pragma unroll
            for (int r = 0; r < 4; r++) acc[mi][ni][r] = 0.f;
    float p[8];
#pragma unroll
    for (int j = 0; j < 8; j++) p[j] = 0.f;

#pragma unroll 1
    for (int s = 0; s < NUM_S; s++) {
        const int kt = s & 15;
        const int nc = s >> 4;
        if (tid == 0 && s + NSTAGES - 1 < NUM_S) {
            int sp = s + NSTAGES - 1;
            uint32_t mb = sb + OFF_MBAR + (sp % NSTAGES) * 8;
            uint32_t dst = sb + (sp % NSTAGES) * STAGE_BYTES;
            mbar_expect_tx(mb, STAGE_BYTES);
            bulk_cp(dst, encT + (size_t)(sp & 15) * 16384, 16384, mb);
            bulk_cp(dst + 16384, vtT + ((size_t)sp << 14), 16384, mb);
        }
        if (kt == 0) {
            sdp[tid] = g_dp[bidx * C_DIM + nc * N_CHUNK + tid];
            sw[tid] = w_vec[nc * N_CHUNK + tid];
        }
        mbar_wait(sb + OFF_MBAR + (s % NSTAGES) * 8, (s / NSTAGES) & 1);

        uint32_t stA = sb + (s % NSTAGES) * STAGE_BYTES;
        uint32_t stB = stA + 16384;
#pragma unroll
        for (int ks = 0; ks < 4; ks++) {
            const uint32_t kx = (uint32_t)(ks * 32);
            uint32_t af[4][4];
#pragma unroll
            for (int mi = 0; mi < 4; mi++)
                ldsm4(af[mi][0], af[mi][1], af[mi][2], af[mi][3],
                      stA + (a_off[mi] ^ kx));
            uint32_t bf[4][4];
#pragma unroll
            for (int bg = 0; bg < 4; bg++)
                ldsm4(bf[bg][0], bf[bg][1], bf[bg][2], bf[bg][3],
                      stB + (b_off[bg] ^ kx));
#pragma unroll
            for (int mi = 0; mi < 4; mi++)
#pragma unroll
                for (int ni = 0; ni < 8; ni++) {
                    int bg = ni >> 1, sub = (ni & 1) * 2;
                    mma16816(acc[mi][ni], af[mi][0], af[mi][1], af[mi][2],
                             af[mi][3], bf[bg][sub], bf[bg][sub + 1]);
                }
        }

        if (kt == 15) {
#pragma unroll
            for (int mi = 0; mi < 4; mi++)
#pragma unroll
                for (int ni = 0; ni < 8; ni++) {
                    int col = warp_n * 64 + ni * 8 + (lane & 3) * 2;
                    float d0 = sdp[col], d1 = sdp[col + 1];
                    float w0 = sw[col], w1 = sw[col + 1];
                    float* c = acc[mi][ni];
                    p[mi * 2 + 0] += tanh_ap(c[0] + d0) * w0 + tanh_ap(c[1] + d1) * w1;
                    p[mi * 2 + 1] += tanh_ap(c[2] + d0) * w0 + tanh_ap(c[3] + d1) * w1;
                    c[0] = 0.f; c[1] = 0.f; c[2] = 0.f; c[3] = 0.f;
                }
        }
        __syncthreads();
    }

    // reduction: lane quads (cols within warp), then warp_n pairs via smem
#pragma unroll
    for (int j = 0; j < 8; j++) {
        p[j] += __shfl_xor_sync(0xFFFFFFFF, p[j], 1);
        p[j] += __shfl_xor_sync(0xFFFFFFFF, p[j], 2);
    }
    if (warp_n == 0 && (lane & 3) == 0) {
#pragma unroll
        for (int j = 0; j < 8; j++) {
            int row = warp_m * 64 + (j >> 1) * 16 + (j & 1) * 8 + (lane >> 2);
            sred[row] = p[j];
        }
    }
    __syncthreads();
    if (warp_n == 1 && (lane & 3) == 0) {
#pragma unroll
        for (int j = 0; j < 8; j++) {
            int row = warp_m * 64 + (j >> 1) * 16 + (j & 1) * 8 + (lane >> 2);
            sred[row] += p[j];
        }
    }
    __syncthreads();
    g_scores[m_base + tid] = sred[tid];
}

// -------------------------------- launcher ---------------------------------

extern "C" void kernel_launch(void* const* d_in, const int* in_sizes, int n_in,
                              void* d_out, int out_size) {
    const float* dec  = (const float*)d_in[0];
    const float* enc  = (const float*)d_in[1];
    const float* W    = (const float*)d_in[2];
    const float* V    = (const float*)d_in[3];
    const float* bias = (const float*)d_in[4];
    const float* w    = (const float*)d_in[5];
    float* out = (float*)d_out;

    cudaFuncSetAttribute(gemm_scores_kernel,
                         cudaFuncAttributeMaxDynamicSharedMemorySize, SMEM_TOTAL);

    convert_enc_kernel<<<32768, 256>>>(enc);
    transpose_kernel<<<dim3(32, 32), dim3(32, 8)>>>(V);
    dp_part_kernel<<<dim3(8, 4), 128>>>(dec, W);
    dp_reduce_kernel<<<128, 256>>>(bias);
    gemm_scores_kernel<<<GEMM_CTAS, GEMM_THREADS, SMEM_TOTAL>>>(w);
    softmax_kernel<<<32, 256>>>();
    context_kernel<<<dim3(4, 32), 256>>>(enc, out);
}

// round 7
// speedup vs baseline: 1.2058x; 1.1295x over previous
#include <cuda_runtime.h>
#include <cuda_fp16.h>
#include <cstdint>

// ---------------------------------------------------------------------------
// Bahdanau additive attention, B=32, T=2048, H=C=1024.
// R7: persistent GEMM (grid=296=2/SM), work units = (mtile, nc-pair) -> 2048
// units statically striped across CTAs (kills the 14% wave-quantization loss
// of grid=512@cap296). Scores combined with atomicAdd; g_scores zeroed each
// replay. context_kernel now reads the fp16 tiled enc copy (halved traffic).
// ---------------------------------------------------------------------------

#define B_DIM 32
#define T_DIM 2048
#define H_DIM 1024
#define C_DIM 1024
#define M_TOTAL (B_DIM * T_DIM)      // 65536

#define CTA_M 128
#define N_CHUNK 128
#define NUM_NC (C_DIM / N_CHUNK)     // 8
#define K_STAGE 64
#define NUM_KT (H_DIM / K_STAGE)     // 16
#define NUM_MTILES (M_TOTAL / CTA_M) // 512
#define NUM_UNITS (NUM_MTILES * 4)   // 2048 (mtile x nc-pair)
#define GEMM_CTAS 296                // 2 per SM x 148
#define GEMM_THREADS 128             // 4 warps: 2(M) x 2(N), warp tile 64x64

#define STAGE_BYTES 32768            // A 16KB + B 16KB
#define NSTAGES 3
#define OFF_MBAR (NSTAGES * STAGE_BYTES)
#define OFF_DP (OFF_MBAR + 64)
#define OFF_W (OFF_DP + 512)
#define OFF_RED (OFF_W + 512)
#define SMEM_TOTAL (OFF_RED + 512)   // 99904 (2 CTAs/SM: 199808 <= 227KB)

// scratch (static device arrays; no cudaMalloc allowed)
__device__ __align__(1024) __half g_encHT[(size_t)M_TOTAL * H_DIM];
__device__ __align__(1024) __half g_VtHT[(size_t)C_DIM * H_DIM];
__device__ float g_dpp[4][B_DIM * C_DIM];
__device__ float g_dp[B_DIM * C_DIM];
__device__ float g_scores[M_TOTAL];
__device__ float g_align[M_TOTAL];

#define SW128(o) ((o) ^ (((o) >> 3) & 0x70))

// ------------------------------- PTX helpers -------------------------------

__device__ __forceinline__ uint32_t smem_u32(const void* p) {
    uint32_t a;
    asm("{ .reg .u64 t; cvta.to.shared.u64 t, %1; cvt.u32.u64 %0, t; }" : "=r"(a) : "l"(p));
    return a;
}

__device__ __forceinline__ void bulk_cp(uint32_t dst, const void* src,
                                        uint32_t bytes, uint32_t mbar) {
    asm volatile(
        "cp.async.bulk.shared::cluster.global.mbarrier::complete_tx::bytes "
        "[%0], [%1], %2, [%3];"
        :: "r"(dst), "l"(src), "r"(bytes), "r"(mbar) : "memory");
}

__device__ __forceinline__ void mbar_init(uint32_t a, uint32_t cnt) {
    asm volatile("mbarrier.init.shared.b64 [%0], %1;" :: "r"(a), "r"(cnt) : "memory");
}

__device__ __forceinline__ void mbar_expect_tx(uint32_t a, uint32_t n) {
    asm volatile("mbarrier.arrive.expect_tx.shared.b64 _, [%0], %1;"
                 :: "r"(a), "r"(n) : "memory");
}

__device__ __forceinline__ void mbar_wait(uint32_t a, uint32_t phase) {
    asm volatile(
        "{\n\t.reg .pred P;\n"
        "WL_%=:\n\t"
        "mbarrier.try_wait.parity.acquire.cta.shared::cta.b64 P, [%0], %1, 0x989680;\n\t"
        "@P bra WD_%=;\n\t"
        "bra WL_%=;\n"
        "WD_%=:\n\t}"
        :: "r"(a), "r"(phase) : "memory");
}

__device__ __forceinline__ void ldsm4(uint32_t& r0, uint32_t& r1, uint32_t& r2,
                                      uint32_t& r3, uint32_t addr) {
    asm volatile("ldmatrix.sync.aligned.m8n8.x4.shared.b16 {%0,%1,%2,%3}, [%4];"
                 : "=r"(r0), "=r"(r1), "=r"(r2), "=r"(r3) : "r"(addr));
}

__device__ __forceinline__ void mma16816(float* c, uint32_t a0, uint32_t a1,
                                         uint32_t a2, uint32_t a3,
                                         uint32_t b0, uint32_t b1) {
    asm volatile(
        "mma.sync.aligned.m16n8k16.row.col.f32.f16.f16.f32 "
        "{%0,%1,%2,%3}, {%4,%5,%6,%7}, {%8,%9}, {%0,%1,%2,%3};"
        : "+f"(c[0]), "+f"(c[1]), "+f"(c[2]), "+f"(c[3])
        : "r"(a0), "r"(a1), "r"(a2), "r"(a3), "r"(b0), "r"(b1));
}

__device__ __forceinline__ float tanh_ap(float x) {
    float y;
    asm("tanh.approx.f32 %0, %1;" : "=f"(y) : "f"(x));
    return y;
}

// ------------------------------ prep kernels -------------------------------

__global__ void convert_enc_kernel(const float* __restrict__ enc) {
    size_t i = (size_t)blockIdx.x * 256 + threadIdx.x;
    int c16 = (int)(i & 7);
    int row = (int)((i >> 3) & 127);
    int kt = (int)((i >> 10) & 15);
    int mtile = (int)(i >> 14);
    int m = mtile * 128 + row;
    int k = kt * 64 + c16 * 8;
    const float4* s = (const float4*)(enc + (size_t)m * H_DIM + k);
    float4 v0 = s[0], v1 = s[1];
    __half2 h0 = __floats2half2_rn(v0.x, v0.y);
    __half2 h1 = __floats2half2_rn(v0.z, v0.w);
    __half2 h2 = __floats2half2_rn(v1.x, v1.y);
    __half2 h3 = __floats2half2_rn(v1.z, v1.w);
    uint4 u;
    u.x = *(uint32_t*)&h0; u.y = *(uint32_t*)&h1;
    u.z = *(uint32_t*)&h2; u.w = *(uint32_t*)&h3;
    char* dst = (char*)g_encHT + (((size_t)mtile * 16 + kt) << 14) +
                SW128(row * 128 + c16 * 16);
    *(uint4*)dst = u;
}

__global__ void transpose_kernel(const float* __restrict__ V) {
    __shared__ float t[32][33];
    int bx = blockIdx.x, by = blockIdx.y;
    int tx = threadIdx.x, ty = threadIdx.y;
#pragma unroll
    for (int j = 0; j < 32; j += 8)
        t[ty + j][tx] = V[(size_t)(by * 32 + ty + j) * C_DIM + bx * 32 + tx];
    __syncthreads();
#pragma unroll
    for (int j = 0; j < 32; j += 8) {
        int n = bx * 32 + ty + j;
        int k = by * 32 + tx;
        int nc = n >> 7, row = n & 127;
        int kt = k >> 6, c16 = (k >> 3) & 7, r8 = k & 7;
        size_t off = (((size_t)nc * 16 + kt) << 14) +
                     SW128(row * 128 + c16 * 16) + r8 * 2;
        *(__half*)((char*)g_VtHT + off) = __float2half(t[tx][ty + j]);
    }
}

__global__ void dp_part_kernel(const float* __restrict__ dec,
                               const float* __restrict__ W) {
    __shared__ float sdec[32 * 256];
    int cb = blockIdx.x, hc = blockIdx.y;
    int tid = threadIdx.x;
    for (int i = tid; i < 32 * 256; i += 128) {
        int b = i >> 8, h = i & 255;
        sdec[i] = dec[b * H_DIM + hc * 256 + h];
    }
    __syncthreads();
    int c = cb * 128 + tid;
    float acc[32];
#pragma unroll
    for (int b = 0; b < 32; b++) acc[b] = 0.f;
#pragma unroll 4
    for (int h = 0; h < 256; h++) {
        float wv = W[(size_t)(hc * 256 + h) * C_DIM + c];
#pragma unroll
        for (int b = 0; b < 32; b++) acc[b] += sdec[b * 256 + h] * wv;
    }
#pragma unroll
    for (int b = 0; b < 32; b++) g_dpp[hc][b * C_DIM + c] = acc[b];
}

// also zeroes g_scores (needed every graph replay: GEMM uses atomicAdd)
__global__ void dp_reduce_kernel(const float* __restrict__ bias) {
    int i = blockIdx.x * 256 + threadIdx.x;  // 32768 entries
    int c = i & (C_DIM - 1);
    g_dp[i] = bias[c] + g_dpp[0][i] + g_dpp[1][i] + g_dpp[2][i] + g_dpp[3][i];
    g_scores[i] = 0.f;
    g_scores[i + 32768] = 0.f;
}

__global__ void softmax_kernel() {
    int b = blockIdx.x, tid = threadIdx.x;
    __shared__ float red[256];
    float v[8];
    float m = -1e30f;
#pragma unroll
    for (int k = 0; k < 8; k++) {
        v[k] = g_scores[b * T_DIM + k * 256 + tid];
        m = fmaxf(m, v[k]);
    }
    red[tid] = m;
    __syncthreads();
    for (int s = 128; s > 0; s >>= 1) {
        if (tid < s) red[tid] = fmaxf(red[tid], red[tid + s]);
        __syncthreads();
    }
    m = red[0];
    __syncthreads();
    float sum = 0.f;
#pragma unroll
    for (int k = 0; k < 8; k++) {
        v[k] = __expf(v[k] - m);
        sum += v[k];
    }
    red[tid] = sum;
    __syncthreads();
    for (int s = 128; s > 0; s >>= 1) {
        if (tid < s) red[tid] += red[tid + s];
        __syncthreads();
    }
    float inv = 1.f / red[0];
#pragma unroll
    for (int k = 0; k < 8; k++) g_align[b * T_DIM + k * 256 + tid] = v[k] * inv;
}

// context from the fp16 tiled enc copy (128MB instead of 256MB fp32).
// block = (kt, b); 256 threads = 8 warps; lane owns h-pair (2 halves = 4B).
__global__ void context_kernel(float* __restrict__ out) {
    int kt = blockIdx.x, b = blockIdx.y;
    int tid = threadIdx.x;
    int wid = tid >> 5, lane = tid & 31;
    __shared__ float sal[128];
    __shared__ float red[8][64];
    float ax = 0.f, ay = 0.f;
    const uint32_t inoff = SW128((lane >> 2) * 16) + (lane & 3) * 4;
#pragma unroll 1
    for (int i = 0; i < 16; i++) {
        const char* tile = (const char*)g_encHT +
                           (((size_t)(b * 16 + i) * 16 + kt) << 14);
        if (tid < 128) sal[tid] = g_align[b * T_DIM + i * 128 + tid];
        __syncthreads();
#pragma unroll 4
        for (int r = wid; r < 128; r += 8) {
            // SW128(r*128 + x) == r*128 + SW128(x) with row-dependent XOR on x:
            // full recompute to stay safe:
            uint32_t off = SW128((uint32_t)(r * 128 + (lane >> 2) * 16)) + (lane & 3) * 4;
            __half2 hv = *(const __half2*)(tile + off);
            float2 f = __half22float2(hv);
            float a = sal[r];
            ax += a * f.x;
            ay += a * f.y;
        }
        __syncthreads();
    }
    red[wid][lane * 2] = ax;
    red[wid][lane * 2 + 1] = ay;
    __syncthreads();
    if (tid < 64) {
        float s = 0.f;
#pragma unroll
        for (int w = 0; w < 8; w++) s += red[w][tid];
        out[b * H_DIM + kt * 64 + tid] = s;
    }
    (void)inoff;
}

// ------------------------------- GEMM kernel -------------------------------
// Persistent: 296 CTAs, unit = (mtile, nc-pair). CTA k does units k+296j.
// Continuous 3-stage bulk-copy ring across unit boundaries. 4 warps (2Mx2N),
// warp tile 64x64. Fused tanh(ep+dp)*w epilogue; atomicAdd score partials.

__global__ void __launch_bounds__(GEMM_THREADS)
gemm_scores_kernel(const float* __restrict__ w_vec) {
    extern __shared__ __align__(1024) char smem[];
    uint32_t sb = smem_u32(smem);
    const int tid = threadIdx.x;
    const int lane = tid & 31;
    const int wid = tid >> 5;
    const int warp_m = wid & 1;
    const int warp_n = wid >> 1;
    const int bid = blockIdx.x;

    float* sdp = (float*)(smem + OFF_DP);
    float* sw = (float*)(smem + OFF_W);
    float* sred = (float*)(smem + OFF_RED);

    // ldmatrix base addresses (swizzled; XOR ks*32 per k16-step)
    uint32_t a_off[4];
#pragma unroll
    for (int mi = 0; mi < 4; mi++) {
        int ar = warp_m * 64 + mi * 16 + (lane & 15);
        a_off[mi] = SW128(ar * 128 + (lane >> 4) * 16);
    }
    const int b_row_in = (lane & 7) + ((lane >> 4) & 1) * 8;
    const uint32_t b_koff = ((lane >> 3) & 1) * 16;
    uint32_t b_off[4];
#pragma unroll
    for (int bg = 0; bg < 4; bg++) {
        int brow = warp_n * 64 + bg * 16 + b_row_in;
        b_off[bg] = SW128(brow * 128 + b_koff);
    }

    const char* encT = (const char*)g_encHT;
    const char* vtT = (const char*)g_VtHT;

    const int n_units = (NUM_UNITS - bid + GEMM_CTAS - 1) / GEMM_CTAS;
    const int total_stages = n_units * 32;

    if (tid == 0) {
#pragma unroll
        for (int b = 0; b < NSTAGES; b++) mbar_init(sb + OFF_MBAR + b * 8, 1);
    }
    __syncthreads();

// stage s -> gmem sources
#define STAGE_SRC(s, asrc, bsrc)                                          \
    {                                                                     \
        int u_ = bid + ((s) >> 5) * GEMM_CTAS;                            \
        int mtile_ = u_ >> 2;                                             \
        int loc_ = (s) & 31;                                              \
        int nc_ = (u_ & 3) * 2 + (loc_ >> 4);                             \
        int kt_ = loc_ & 15;                                              \
        asrc = encT + (((size_t)mtile_ * 16 + kt_) << 14);                \
        bsrc = vtT + (((size_t)nc_ * 16 + kt_) << 14);                    \
    }

    if (tid == 0) {
#pragma unroll
        for (int s = 0; s < NSTAGES - 1; s++) {
            const char *as_, *bs_;
            STAGE_SRC(s, as_, bs_);
            uint32_t mb = sb + OFF_MBAR + s * 8;
            uint32_t dst = sb + s * STAGE_BYTES;
            mbar_expect_tx(mb, STAGE_BYTES);
            bulk_cp(dst, as_, 16384, mb);
            bulk_cp(dst + 16384, bs_, 16384, mb);
        }
    }

    float acc[4][8][4];
#pragma unroll
    for (int mi = 0; mi < 4; mi++)
#pragma unroll
        for (int ni = 0; ni < 8; ni++)
#pragma unroll
            for (int r = 0; r < 4; r++) acc[mi][ni][r] = 0.f;
    float p[8];
#pragma unroll
    for (int j = 0; j < 8; j++) p[j] = 0.f;

#pragma unroll 1
    for (int s = 0; s < total_stages; s++) {
        const int u = bid + (s >> 5) * GEMM_CTAS;
        const int mtile = u >> 2;
        const int loc = s & 31;
        const int nc = (u & 3) * 2 + (loc >> 4);
        const int kt = loc & 15;
        const int bidx = mtile >> 4;

        if (tid == 0 && s + NSTAGES - 1 < total_stages) {
            const int sp = s + NSTAGES - 1;
            const char *as_, *bs_;
            STAGE_SRC(sp, as_, bs_);
            uint32_t mb = sb + OFF_MBAR + (sp % NSTAGES) * 8;
            uint32_t dst = sb + (sp % NSTAGES) * STAGE_BYTES;
            mbar_expect_tx(mb, STAGE_BYTES);
            bulk_cp(dst, as_, 16384, mb);
            bulk_cp(dst + 16384, bs_, 16384, mb);
        }
        if (kt == 0) {
            sdp[tid] = g_dp[bidx * C_DIM + nc * N_CHUNK + tid];
            sw[tid] = w_vec[nc * N_CHUNK + tid];
        }
        mbar_wait(sb + OFF_MBAR + (s % NSTAGES) * 8, (s / NSTAGES) & 1);

        uint32_t stA = sb + (s % NSTAGES) * STAGE_BYTES;
        uint32_t stB = stA + 16384;
#pragma unroll
        for (int ks = 0; ks < 4; ks++) {
            const uint32_t kx = (uint32_t)(ks * 32);
            uint32_t af[4][4];
#pragma unroll
            for (int mi = 0; mi < 4; mi++)
                ldsm4(af[mi][0], af[mi][1], af[mi][2], af[mi][3],
                      stA + (a_off[mi] ^ kx));
            uint32_t bf[4][4];
#pragma unroll
            for (int bg = 0; bg < 4; bg++)
                ldsm4(bf[bg][0], bf[bg][1], bf[bg][2], bf[bg][3],
                      stB + (b_off[bg] ^ kx));
#pragma unroll
            for (int mi = 0; mi < 4; mi++)
#pragma unroll
                for (int ni = 0; ni < 8; ni++) {
                    int bg = ni >> 1, sub = (ni & 1) * 2;
                    mma16816(acc[mi][ni], af[mi][0], af[mi][1], af[mi][2],
                             af[mi][3], bf[bg][sub], bf[bg][sub + 1]);
                }
        }

        if (kt == 15) {
            // fused epilogue: p += tanh(ep+dp)*w; reset accumulators
#pragma unroll
            for (int mi = 0; mi < 4; mi++)
#pragma unroll
                for (int ni = 0; ni < 8; ni++) {
                    int col = warp_n * 64 + ni * 8 + (lane & 3) * 2;
                    float d0 = sdp[col], d1 = sdp[col + 1];
                    float w0 = sw[col], w1 = sw[col + 1];
                    float* c = acc[mi][ni];
                    p[mi * 2 + 0] += tanh_ap(c[0] + d0) * w0 + tanh_ap(c[1] + d1) * w1;
                    p[mi * 2 + 1] += tanh_ap(c[2] + d0) * w0 + tanh_ap(c[3] + d1) * w1;
                    c[0] = 0.f; c[1] = 0.f; c[2] = 0.f; c[3] = 0.f;
                }
        }
        if (loc == 31) {
            // end of unit: reduce p and add into g_scores
#pragma unroll
            for (int j = 0; j < 8; j++) {
                p[j] += __shfl_xor_sync(0xFFFFFFFF, p[j], 1);
                p[j] += __shfl_xor_sync(0xFFFFFFFF, p[j], 2);
            }
            if (warp_n == 0 && (lane & 3) == 0) {
#pragma unroll
                for (int j = 0; j < 8; j++) {
                    int row = warp_m * 64 + (j >> 1) * 16 + (j & 1) * 8 + (lane >> 2);
                    sred[row] = p[j];
                }
            }
            __syncthreads();
            if (warp_n == 1 && (lane & 3) == 0) {
#pragma unroll
                for (int j = 0; j < 8; j++) {
                    int row = warp_m * 64 + (j >> 1) * 16 + (j & 1) * 8 + (lane >> 2);
                    sred[row] += p[j];
                }
            }
            __syncthreads();
            atomicAdd(&g_scores[mtile * CTA_M + tid], sred[tid]);
#pragma unroll
            for (int j = 0; j < 8; j++) p[j] = 0.f;
        }
        __syncthreads();
    }
#undef STAGE_SRC
}

// -------------------------------- launcher ---------------------------------

extern "C" void kernel_launch(void* const* d_in, const int* in_sizes, int n_in,
                              void* d_out, int out_size) {
    const float* dec  = (const float*)d_in[0];
    const float* enc  = (const float*)d_in[1];
    const float* W    = (const float*)d_in[2];
    const float* V    = (const float*)d_in[3];
    const float* bias = (const float*)d_in[4];
    const float* w    = (const float*)d_in[5];
    float* out = (float*)d_out;

    cudaFuncSetAttribute(gemm_scores_kernel,
                         cudaFuncAttributeMaxDynamicSharedMemorySize, SMEM_TOTAL);

    convert_enc_kernel<<<32768, 256>>>(enc);
    transpose_kernel<<<dim3(32, 32), dim3(32, 8)>>>(V);
    dp_part_kernel<<<dim3(8, 4), 128>>>(dec, W);
    dp_reduce_kernel<<<128, 256>>>(bias);
    gemm_scores_kernel<<<GEMM_CTAS, GEMM_THREADS, SMEM_TOTAL>>>(w);
    softmax_kernel<<<32, 256>>>();
    context_kernel<<<dim3(16, 32), 256>>>(out);
}